// round 2
// baseline (speedup 1.0000x reference)
#include <cuda_runtime.h>
#include <cuda_bf16.h>

#define BB 16
#define NN 256
#define DD 512
#define PE_ROWS 64   // pos = t - start < x[b,seg] <= 63, so only rows 0..63 are gathered

// Single persistent kernel: each CTA
//   1) stages pos_enc rows 0..63 (128 KB) into smem
//   2) warp-scans x (16 rows x 256) into its own smem cumsum table (16 KB)
//   3) grid-strides over (b,t) output rows: 9-step binary search + 2 KB float4 copy
__global__ __launch_bounds__(1024, 1)
void pe_gather_kernel(const int* __restrict__ x,
                      const float* __restrict__ pos_enc,
                      float* __restrict__ out, int T) {
    extern __shared__ float smem[];
    float* s_pe  = smem;                                // PE_ROWS * DD floats (128 KB)
    int*   s_cum = (int*)(smem + PE_ROWS * DD);         // BB * NN ints (16 KB)

    const int warp = threadIdx.x >> 5;
    const int lane = threadIdx.x & 31;

    // ---- stage hot pos_enc rows ----
    {
        const float4* src = (const float4*)pos_enc;
        float4* dst = (float4*)s_pe;
        for (int i = threadIdx.x; i < PE_ROWS * DD / 4; i += blockDim.x)
            dst[i] = src[i];
    }

    // ---- per-CTA cumsum of x: warps 0..15 each scan one batch row ----
    if (warp < BB) {
        int carry = 0;
        for (int chunk = 0; chunk < NN / 32; chunk++) {
            int idx = chunk * 32 + lane;
            int v = x[warp * NN + idx];
            #pragma unroll
            for (int off = 1; off < 32; off <<= 1) {
                int n = __shfl_up_sync(0xffffffffu, v, off);
                if (lane >= off) v += n;
            }
            v += carry;
            s_cum[warp * NN + idx] = v;
            carry = __shfl_sync(0xffffffffu, v, 31);
        }
    }
    __syncthreads();

    // ---- main loop: one warp per output row ----
    const int warp_global = blockIdx.x * (blockDim.x >> 5) + warp;
    const int nwarps = gridDim.x * (blockDim.x >> 5);
    const long total_pairs = (long)BB * T;

    for (long p = warp_global; p < total_pairs; p += nwarps) {
        const int b = (int)(p / T);
        const int t = (int)(p % T);
        const int* cum = s_cum + b * NN;
        float4* dst = (float4*)(out + p * (long)DD);

        if (t >= cum[NN - 1]) {
            // past this batch-row's total frames -> zeros
            const float4 z = make_float4(0.f, 0.f, 0.f, 0.f);
            #pragma unroll
            for (int i = 0; i < 4; i++) dst[lane + 32 * i] = z;
        } else {
            // searchsorted(cum, t, side='right'): first i with cum[i] > t.
            // Answer space is [0,256] -> 257 candidates -> needs 9 halvings.
            int lo = 0, hi = NN;
            #pragma unroll
            for (int it = 0; it < 9; it++) {
                if (lo < hi) {
                    int mid = (lo + hi) >> 1;
                    if (cum[mid] <= t) lo = mid + 1; else hi = mid;
                }
            }
            const int seg = lo;                          // <= NN-1 since t < cum[NN-1]
            const int start = (seg > 0) ? cum[seg - 1] : 0;
            const int pos = t - start;                   // in [0, 62] by construction
            const float4* src = (const float4*)(s_pe + pos * DD);
            #pragma unroll
            for (int i = 0; i < 4; i++) dst[lane + 32 * i] = src[lane + 32 * i];
        }
    }
}

extern "C" void kernel_launch(void* const* d_in, const int* in_sizes, int n_in,
                              void* d_out, int out_size) {
    const int*   x       = (const int*)d_in[0];
    const float* pos_enc = (const float*)d_in[1];
    float*       out     = (float*)d_out;

    const int T = out_size / (BB * DD);

    const size_t smem_bytes = (size_t)(PE_ROWS * DD) * sizeof(float)
                            + (size_t)(BB * NN) * sizeof(int);   // 147456 B
    cudaFuncSetAttribute(pe_gather_kernel,
                         cudaFuncAttributeMaxDynamicSharedMemorySize,
                         (int)smem_bytes);
    pe_gather_kernel<<<152, 1024, smem_bytes>>>(x, pos_enc, out, T);
}